// round 6
// baseline (speedup 1.0000x reference)
#include <cuda_runtime.h>
#include <cuda_fp16.h>
#include <math.h>

// B=4, H=8, N=128, Lq=Lk=128, D=64. Persistent CTAs; 8 warps; warp owns 16 q rows.
// Double-buffered smem: compute problem p from buf while staging p+stride into buf^1.
#define LSEQ 128
#define DH   64
#define NTHREADS 256
#define SSTRIDE 72                     // halves; 144B row stride -> conflict-free
#define BUFH (3 * LSEQ * SSTRIDE)      // halves per buffer (Q,K,V) = 27648
#define TEN  (LSEQ * SSTRIDE)          // halves per tensor = 9216

// Packed mask bits: B*N*L*L / 32 = 262144 words (1 MB) for the fixed shapes.
__device__ unsigned int g_pmask[262144];

// One thread per int4 (4 ints -> 1 nibble); 3 shuffle rounds build each 32-bit word
// from 8 lanes. Lane 8k stores word k of the warp's 128 ints.
__global__ void pack_mask_kernel(const int* __restrict__ mask, int nquads)
{
    const int idx  = blockIdx.x * blockDim.x + threadIdx.x;
    const int lane = threadIdx.x & 31;
    if (idx < nquads) {
        const int4 q = ((const int4*)mask)[idx];
        unsigned int v = (unsigned)(q.x != 0) | ((unsigned)(q.y != 0) << 1)
                       | ((unsigned)(q.z != 0) << 2) | ((unsigned)(q.w != 0) << 3);
        v |= __shfl_xor_sync(0xffffffffu, v, 1) << 4;    // valid on even lanes
        v |= __shfl_xor_sync(0xffffffffu, v, 2) << 8;    // valid on lanes %4==0
        v |= __shfl_xor_sync(0xffffffffu, v, 4) << 16;   // valid on lanes %8==0
        if ((lane & 7) == 0)
            g_pmask[(idx >> 3)] = v;   // idx/8 = global word index
    }
}

__device__ __forceinline__ void ldsm_x4(unsigned int* r, const __half* p)
{
    unsigned int a = (unsigned int)__cvta_generic_to_shared(p);
    asm volatile("ldmatrix.sync.aligned.m8n8.x4.shared.b16 {%0,%1,%2,%3}, [%4];"
                 : "=r"(r[0]), "=r"(r[1]), "=r"(r[2]), "=r"(r[3]) : "r"(a));
}

__device__ __forceinline__ void ldsm_x4_trans(unsigned int* r, const __half* p)
{
    unsigned int a = (unsigned int)__cvta_generic_to_shared(p);
    asm volatile("ldmatrix.sync.aligned.m8n8.x4.trans.shared.b16 {%0,%1,%2,%3}, [%4];"
                 : "=r"(r[0]), "=r"(r[1]), "=r"(r[2]), "=r"(r[3]) : "r"(a));
}

__device__ __forceinline__ void mma_f16(float* d, const unsigned int* a,
                                        unsigned int b0, unsigned int b1)
{
    asm volatile(
        "mma.sync.aligned.m16n8k16.row.col.f32.f16.f16.f32 "
        "{%0,%1,%2,%3}, {%4,%5,%6,%7}, {%8,%9}, {%0,%1,%2,%3};"
        : "+f"(d[0]), "+f"(d[1]), "+f"(d[2]), "+f"(d[3])
        : "r"(a[0]), "r"(a[1]), "r"(a[2]), "r"(a[3]), "r"(b0), "r"(b1));
}

__device__ __forceinline__ unsigned int h2u(__half2 h)
{
    union { __half2 h; unsigned int u; } c; c.h = h; return c.u;
}

// Stage chunk c (quarter) of one problem's Q/K/V into the given fp16 buffer.
__device__ __forceinline__ void stage_chunk(const float4* __restrict__ qg,
                                            const float4* __restrict__ kg,
                                            const float4* __restrict__ vg,
                                            __half* __restrict__ buf,
                                            int c, int tid)
{
    __half* Qs = buf;
    __half* Ks = buf + TEN;
    __half* Vs = buf + 2 * TEN;
    #pragma unroll
    for (int r = 0; r < 2; r++) {
        const int i   = c * 512 + r * 256 + tid;   // float4 index, 0..2047
        const int row = i >> 4, c4 = i & 15;
        const int off = row * SSTRIDE + c4 * 4;
        float4 a = qg[i];
        *(__half2*)(Qs + off)     = __floats2half2_rn(a.x, a.y);
        *(__half2*)(Qs + off + 2) = __floats2half2_rn(a.z, a.w);
        float4 kk = kg[i];
        *(__half2*)(Ks + off)     = __floats2half2_rn(kk.x, kk.y);
        *(__half2*)(Ks + off + 2) = __floats2half2_rn(kk.z, kk.w);
        float4 vv = vg[i];
        *(__half2*)(Vs + off)     = __floats2half2_rn(vv.x, vv.y);
        *(__half2*)(Vs + off + 2) = __floats2half2_rn(vv.z, vv.w);
    }
}

__global__ __launch_bounds__(NTHREADS, 2)
void attn_mma_fp16(const float* __restrict__ q,
                   const float* __restrict__ k,
                   const float* __restrict__ v,
                   float*       __restrict__ out,
                   int HN, int nprob)
{
    extern __shared__ __align__(16) char smraw[];
    __half* bufs = (__half*)smraw;     // two buffers of BUFH halves

    const int tid  = threadIdx.x;
    const int wid  = tid >> 5;         // 0..7, warp owns rows [16*wid, 16*wid+16)
    const int lane = tid & 31;
    const int g    = lane >> 2;
    const int t    = lane & 3;
    const int stride = gridDim.x;

    int buf = 0;

    // ---- prologue: stage first problem fully into buffer 0 ----
    {
        const size_t base0 = (size_t)blockIdx.x * (LSEQ * DH);
        const float4* qg = (const float4*)(q + base0);
        const float4* kg = (const float4*)(k + base0);
        const float4* vg = (const float4*)(v + base0);
        #pragma unroll
        for (int c = 0; c < 4; c++)
            stage_chunk(qg, kg, vg, bufs, c, tid);
    }
    __syncthreads();

    // ================= persistent loop over problems =================
    for (int p = blockIdx.x; p < nprob; p += stride) {
        const int  pn       = p + stride;
        const bool has_next = pn < nprob;
        const size_t base   = (size_t)p * (LSEQ * DH);
        const size_t basen  = (size_t)(has_next ? pn : p) * (LSEQ * DH);
        const float4* qn = (const float4*)(q + basen);
        const float4* kn = (const float4*)(k + basen);
        const float4* vn = (const float4*)(v + basen);

        __half* Qs = bufs + buf * BUFH;
        __half* Ks = Qs + TEN;
        __half* Vs = Qs + 2 * TEN;
        __half* nbuf = bufs + (buf ^ 1) * BUFH;

        const int b = p / HN;
        const int n = p % LSEQ;

        // packed mask bits for this thread's 2 rows (h=0,1)
        uint4 mw[2];
        #pragma unroll
        for (int h = 0; h < 2; h++) {
            const int rr = 16 * wid + g + 8 * h;
            mw[h] = *(const uint4*)(g_pmask +
                     ((size_t)((b * LSEQ + n) * LSEQ + rr)) * 4);
        }

        // Q A-fragments via ldmatrix
        unsigned int qa[4][4];
        #pragma unroll
        for (int ks = 0; ks < 4; ks++) {
            const __half* ptr = Qs + (16 * wid + (lane & 15)) * SSTRIDE
                                   + 16 * ks + ((lane & 16) >> 1);
            ldsm_x4(qa[ks], ptr);
        }

        float mrow[2] = { -INFINITY, -INFINITY };
        float lrow[2] = { 0.0f, 0.0f };
        float oacc[8][4];
        #pragma unroll
        for (int nt = 0; nt < 8; nt++)
            for (int e = 0; e < 4; e++) oacc[nt][e] = 0.0f;

        // ---- 4 key-blocks of 32; each also stages 1/4 of the next problem ----
        #pragma unroll 1
        for (int kb = 0; kb < 4; kb++) {
            const int key0 = kb * 32;

            // S = Q @ K^T
            float sfr[4][4];
            #pragma unroll
            for (int nt = 0; nt < 4; nt++)
                for (int e = 0; e < 4; e++) sfr[nt][e] = 0.0f;

            #pragma unroll
            for (int ntp = 0; ntp < 2; ntp++) {
                #pragma unroll
                for (int ks = 0; ks < 4; ks++) {
                    unsigned int kb4[4];
                    const __half* kp = Ks + (key0 + 16 * ntp + ((lane & 16) >> 1) + (lane & 7)) * SSTRIDE
                                          + 16 * ks + (lane & 8);
                    ldsm_x4(kb4, kp);
                    mma_f16(sfr[2 * ntp],     qa[ks], kb4[0], kb4[1]);
                    mma_f16(sfr[2 * ntp + 1], qa[ks], kb4[2], kb4[3]);
                }
            }

            // scale + mask + row max
            float bm[2] = { -INFINITY, -INFINITY };
            #pragma unroll
            for (int h = 0; h < 2; h++) {
                const uint4 m4 = mw[h];
                const unsigned int w = (kb == 0) ? m4.x : (kb == 1) ? m4.y
                                     : (kb == 2) ? m4.z : m4.w;
                #pragma unroll
                for (int nt = 0; nt < 4; nt++) {
                    const unsigned int sh = (unsigned)(8 * nt + 2 * t);
                    const bool b0 = (w >> sh) & 1u;
                    const bool b1 = (w >> (sh + 1)) & 1u;
                    float e0 = sfr[nt][2 * h];
                    float e1 = sfr[nt][2 * h + 1];
                    e0 = b0 ? e0 * 0.125f : -32768.0f;
                    e1 = b1 ? e1 * 0.125f : -32768.0f;
                    sfr[nt][2 * h]     = e0;
                    sfr[nt][2 * h + 1] = e1;
                    bm[h] = fmaxf(bm[h], fmaxf(e0, e1));
                }
            }
            #pragma unroll
            for (int h = 0; h < 2; h++) {
                float x = bm[h];
                x = fmaxf(x, __shfl_xor_sync(0xffffffff, x, 1));
                x = fmaxf(x, __shfl_xor_sync(0xffffffff, x, 2));
                bm[h] = x;
            }

            // online update
            float alpha[2];
            float rs[2] = { 0.f, 0.f };
            #pragma unroll
            for (int h = 0; h < 2; h++) {
                const float mnew = fmaxf(mrow[h], bm[h]);
                alpha[h] = __expf(mrow[h] - mnew);   // 0 on first block
                mrow[h] = mnew;
            }

            #pragma unroll
            for (int nt = 0; nt < 4; nt++)
                #pragma unroll
                for (int h = 0; h < 2; h++) {
                    float p0 = __expf(sfr[nt][2 * h]     - mrow[h]);
                    float p1 = __expf(sfr[nt][2 * h + 1] - mrow[h]);
                    sfr[nt][2 * h]     = p0;
                    sfr[nt][2 * h + 1] = p1;
                    rs[h] += p0 + p1;
                }

            #pragma unroll
            for (int h = 0; h < 2; h++) {
                float x = rs[h];
                x += __shfl_xor_sync(0xffffffff, x, 1);
                x += __shfl_xor_sync(0xffffffff, x, 2);
                lrow[h] = lrow[h] * alpha[h] + x;
            }

            #pragma unroll
            for (int nt = 0; nt < 8; nt++) {
                oacc[nt][0] *= alpha[0];
                oacc[nt][1] *= alpha[0];
                oacc[nt][2] *= alpha[1];
                oacc[nt][3] *= alpha[1];
            }

            // P: C-frag pairs ARE the fp16 A-frags
            unsigned int pa[2][4];
            #pragma unroll
            for (int ksp = 0; ksp < 2; ksp++) {
                pa[ksp][0] = h2u(__floats2half2_rn(sfr[2 * ksp][0],     sfr[2 * ksp][1]));
                pa[ksp][1] = h2u(__floats2half2_rn(sfr[2 * ksp][2],     sfr[2 * ksp][3]));
                pa[ksp][2] = h2u(__floats2half2_rn(sfr[2 * ksp + 1][0], sfr[2 * ksp + 1][1]));
                pa[ksp][3] = h2u(__floats2half2_rn(sfr[2 * ksp + 1][2], sfr[2 * ksp + 1][3]));
            }

            // O += P @ V
            #pragma unroll
            for (int ksp = 0; ksp < 2; ksp++) {
                #pragma unroll
                for (int dp = 0; dp < 4; dp++) {
                    unsigned int vb4[4];
                    const __half* vp = Vs + (key0 + 16 * ksp + (lane & 15)) * SSTRIDE
                                          + 16 * dp + ((lane & 16) >> 1);
                    ldsm_x4_trans(vb4, vp);
                    mma_f16(oacc[2 * dp],     pa[ksp], vb4[0], vb4[1]);
                    mma_f16(oacc[2 * dp + 1], pa[ksp], vb4[2], vb4[3]);
                }
            }

            // stage 1/4 of the next problem into the other buffer
            if (has_next)
                stage_chunk(qn, kn, vn, nbuf, kb, tid);
        }

        // ---- epilogue: normalize and store ----
        {
            const float inv0 = 1.0f / lrow[0];
            const float inv1 = 1.0f / lrow[1];
            const int r0 = 16 * wid + g;
            #pragma unroll
            for (int nt = 0; nt < 8; nt++) {
                const int col = 8 * nt + 2 * t;
                float2 lo = { oacc[nt][0] * inv0, oacc[nt][1] * inv0 };
                float2 hi = { oacc[nt][2] * inv1, oacc[nt][3] * inv1 };
                *(float2*)(out + base + (size_t)(r0)     * DH + col) = lo;
                *(float2*)(out + base + (size_t)(r0 + 8) * DH + col) = hi;
            }
        }

        __syncthreads();   // next buffer fully staged; old buffer free
        buf ^= 1;
    }
}

extern "C" void kernel_launch(void* const* d_in, const int* in_sizes, int n_in,
                              void* d_out, int out_size)
{
    const float* q    = (const float*)d_in[0];
    const float* k    = (const float*)d_in[1];
    const float* v    = (const float*)d_in[2];
    const int*   mask = (const int*)d_in[3];
    float*       out  = (float*)d_out;

    const int nprob = in_sizes[0] / (LSEQ * DH);     // B*H*N
    const int nmask = in_sizes[3] / (LSEQ * LSEQ);   // B*N
    const int HN    = (nprob / nmask) * LSEQ;        // H*N

    // pack mask bits: one thread per int4
    const int nquads = in_sizes[3] / 4;
    pack_mask_kernel<<<(nquads + 255) / 256, 256>>>(mask, nquads);

    int nsm = 148;
    cudaDeviceGetAttribute(&nsm, cudaDevAttrMultiProcessorCount, 0);
    int grid = 2 * nsm;
    if (grid > nprob) grid = nprob;

    const int smem_bytes = 2 * BUFH * (int)sizeof(__half);   // 110592
    cudaFuncSetAttribute(attn_mma_fp16,
                         cudaFuncAttributeMaxDynamicSharedMemorySize,
                         smem_bytes);

    attn_mma_fp16<<<grid, NTHREADS, smem_bytes>>>(q, k, v, out, HN, nprob);
}

// round 7
// speedup vs baseline: 1.0028x; 1.0028x over previous
#include <cuda_runtime.h>
#include <cuda_fp16.h>
#include <math.h>

// B=4, H=8, N=128, Lq=Lk=128, D=64. Persistent CTAs; 8 warps; warp owns 16 q rows.
// K/V prefetched 2 blocks ahead via cp.async into an fp32 ring, converted JIT to fp16.
#define LSEQ 128
#define DH   64
#define NTHREADS 256
#define SSTRIDE 72                 // halves; 144B rows -> conflict-free ldmatrix
#define TEN   (LSEQ * SSTRIDE)     // halves per fp16 tensor = 9216
#define RINGF 4096                 // floats per ring slot (K 2048 + V 2048)

// Packed mask bits: B*N*L*L / 32 = 262144 words (1 MB).
__device__ unsigned int g_pmask[262144];

// Each warp packs 4 consecutive words (128 ints): 4 coalesced LDG.32 + 4 ballots.
__global__ void pack_mask_kernel(const int* __restrict__ mask, int nwords)
{
    const int warp = (blockIdx.x * blockDim.x + threadIdx.x) >> 5;
    const int lane = threadIdx.x & 31;
    const int w0 = warp * 4;
    if (w0 < nwords) {
        #pragma unroll
        for (int w = 0; w < 4; w++) {
            const int v = mask[(size_t)(w0 + w) * 32 + lane];
            const unsigned int bal = __ballot_sync(0xffffffffu, v != 0);
            if (lane == w) g_pmask[w0 + w] = bal;
        }
    }
}

__device__ __forceinline__ void cp_async16(float* smem_dst, const float* gsrc)
{
    unsigned int d = (unsigned int)__cvta_generic_to_shared(smem_dst);
    asm volatile("cp.async.ca.shared.global [%0], [%1], 16;" :: "r"(d), "l"(gsrc));
}

__device__ __forceinline__ void cp_commit()
{
    asm volatile("cp.async.commit_group;");
}

__device__ __forceinline__ void cp_wait1()
{
    asm volatile("cp.async.wait_group 1;");
}

__device__ __forceinline__ void ldsm_x4(unsigned int* r, const __half* p)
{
    unsigned int a = (unsigned int)__cvta_generic_to_shared(p);
    asm volatile("ldmatrix.sync.aligned.m8n8.x4.shared.b16 {%0,%1,%2,%3}, [%4];"
                 : "=r"(r[0]), "=r"(r[1]), "=r"(r[2]), "=r"(r[3]) : "r"(a));
}

__device__ __forceinline__ void ldsm_x4_trans(unsigned int* r, const __half* p)
{
    unsigned int a = (unsigned int)__cvta_generic_to_shared(p);
    asm volatile("ldmatrix.sync.aligned.m8n8.x4.trans.shared.b16 {%0,%1,%2,%3}, [%4];"
                 : "=r"(r[0]), "=r"(r[1]), "=r"(r[2]), "=r"(r[3]) : "r"(a));
}

__device__ __forceinline__ void mma_f16(float* d, const unsigned int* a,
                                        unsigned int b0, unsigned int b1)
{
    asm volatile(
        "mma.sync.aligned.m16n8k16.row.col.f32.f16.f16.f32 "
        "{%0,%1,%2,%3}, {%4,%5,%6,%7}, {%8,%9}, {%0,%1,%2,%3};"
        : "+f"(d[0]), "+f"(d[1]), "+f"(d[2]), "+f"(d[3])
        : "r"(a[0]), "r"(a[1]), "r"(a[2]), "r"(a[3]), "r"(b0), "r"(b1));
}

__device__ __forceinline__ unsigned int h2u(__half2 h)
{
    union { __half2 h; unsigned int u; } c; c.h = h; return c.u;
}

// Issue cp.async for chunk c (rows [32c,32c+32) of K and V) of problem at `base`.
__device__ __forceinline__ void issue_chunk(const float* __restrict__ k,
                                            const float* __restrict__ v,
                                            size_t base, int c,
                                            float* __restrict__ slot, int tid)
{
    const float* kg = k + base + (size_t)c * 2048;   // 32 rows * 64 cols
    const float* vg = v + base + (size_t)c * 2048;
    cp_async16(slot + tid * 8,            kg + tid * 8);
    cp_async16(slot + tid * 8 + 4,        kg + tid * 8 + 4);
    cp_async16(slot + 2048 + tid * 8,     vg + tid * 8);
    cp_async16(slot + 2048 + tid * 8 + 4, vg + tid * 8 + 4);
    cp_commit();
}

// Convert fp32 ring slot -> fp16 K/V rows [32c, 32c+32).
__device__ __forceinline__ void convert_chunk(const float* __restrict__ slot,
                                              __half* __restrict__ Ks,
                                              __half* __restrict__ Vs,
                                              int c, int tid)
{
    const float4* sk = (const float4*)slot;
    const float4* sv = (const float4*)(slot + 2048);
    const int row = tid >> 4;            // 0..15
    const int col = (tid & 15) * 4;      // 0..60
    #pragma unroll
    for (int half_ = 0; half_ < 2; half_++) {
        const int r = row + 16 * half_;
        const float4 a = sk[tid + 256 * half_];
        __half* kd = Ks + (32 * c + r) * SSTRIDE + col;
        *(__half2*)(kd)     = __floats2half2_rn(a.x, a.y);
        *(__half2*)(kd + 2) = __floats2half2_rn(a.z, a.w);
        const float4 b = sv[tid + 256 * half_];
        __half* vd = Vs + (32 * c + r) * SSTRIDE + col;
        *(__half2*)(vd)     = __floats2half2_rn(b.x, b.y);
        *(__half2*)(vd + 2) = __floats2half2_rn(b.z, b.w);
    }
}

__global__ __launch_bounds__(NTHREADS, 2)
void attn_mma_fp16(const float* __restrict__ q,
                   const float* __restrict__ k,
                   const float* __restrict__ v,
                   float*       __restrict__ out,
                   int HN, int nprob)
{
    extern __shared__ __align__(16) char smraw[];
    __half* Ks   = (__half*)smraw;                 // [128][SSTRIDE]
    __half* Vs   = Ks + TEN;                       // [128][SSTRIDE]
    float*  ring = (float*)(Vs + TEN);             // 2 slots * RINGF floats

    const int tid  = threadIdx.x;
    const int wid  = tid >> 5;          // warp owns rows [16*wid, 16*wid+16)
    const int lane = tid & 31;
    const int g    = lane >> 2;
    const int t    = lane & 3;
    const int stride = gridDim.x;

    // ---- prologue: prefetch chunks 0,1 of the first problem ----
    {
        const size_t base0 = (size_t)blockIdx.x * (LSEQ * DH);
        issue_chunk(k, v, base0, 0, ring, tid);
        issue_chunk(k, v, base0, 1, ring + RINGF, tid);
    }

    // ================= persistent loop over problems =================
    for (int p = blockIdx.x; p < nprob; p += stride) {
        const int  pn       = p + stride;
        const bool has_next = pn < nprob;
        const size_t base   = (size_t)p * (LSEQ * DH);
        const size_t basen  = (size_t)(has_next ? pn : p) * (LSEQ * DH);

        const int b = p / HN;
        const int n = p % LSEQ;

        // packed mask bits for this thread's 2 rows
        uint4 mw[2];
        #pragma unroll
        for (int h = 0; h < 2; h++) {
            const int rr = 16 * wid + g + 8 * h;
            mw[h] = *(const uint4*)(g_pmask +
                     ((size_t)((b * LSEQ + n) * LSEQ + rr)) * 4);
        }

        // Q A-fragments directly from global (quad-coalesced float2 sectors)
        unsigned int qa[4][4];
        {
            const float* qp = q + base;
            const int r0 = 16 * wid + g;
            #pragma unroll
            for (int ks = 0; ks < 4; ks++) {
                const int c = 16 * ks + 2 * t;
                float2 a0 = *(const float2*)(qp + (size_t)(r0)     * DH + c);
                float2 a1 = *(const float2*)(qp + (size_t)(r0 + 8) * DH + c);
                float2 a2 = *(const float2*)(qp + (size_t)(r0)     * DH + c + 8);
                float2 a3 = *(const float2*)(qp + (size_t)(r0 + 8) * DH + c + 8);
                qa[ks][0] = h2u(__floats2half2_rn(a0.x, a0.y));
                qa[ks][1] = h2u(__floats2half2_rn(a1.x, a1.y));
                qa[ks][2] = h2u(__floats2half2_rn(a2.x, a2.y));
                qa[ks][3] = h2u(__floats2half2_rn(a3.x, a3.y));
            }
        }

        float mrow[2] = { -INFINITY, -INFINITY };
        float lrow[2] = { 0.0f, 0.0f };
        float oacc[8][4];
        #pragma unroll
        for (int nt = 0; nt < 8; nt++)
            for (int e = 0; e < 4; e++) oacc[nt][e] = 0.0f;

        // ---- 4 key-blocks of 32, software-pipelined with cp.async ----
        #pragma unroll 1
        for (int kb = 0; kb < 4; kb++) {
            const int key0 = kb * 32;
            float* slot = ring + (kb & 1) * RINGF;

            // chunk kb arrived (issued 2 blocks ago); convert to fp16
            cp_wait1();
            __syncthreads();
            convert_chunk(slot, Ks, Vs, kb, tid);
            __syncthreads();

            // prefetch chunk kb+2 (rolls into the next problem) into this slot
            if (kb < 2) issue_chunk(k, v, base,  kb + 2, slot, tid);
            else        issue_chunk(k, v, basen, kb - 2, slot, tid);

            // ---- S = Q @ K^T ----
            float sfr[4][4];
            #pragma unroll
            for (int nt = 0; nt < 4; nt++)
                for (int e = 0; e < 4; e++) sfr[nt][e] = 0.0f;

            #pragma unroll
            for (int ntp = 0; ntp < 2; ntp++) {
                #pragma unroll
                for (int ks = 0; ks < 4; ks++) {
                    unsigned int kb4[4];
                    const __half* kp = Ks + (key0 + 16 * ntp + ((lane & 16) >> 1) + (lane & 7)) * SSTRIDE
                                          + 16 * ks + (lane & 8);
                    ldsm_x4(kb4, kp);
                    mma_f16(sfr[2 * ntp],     qa[ks], kb4[0], kb4[1]);
                    mma_f16(sfr[2 * ntp + 1], qa[ks], kb4[2], kb4[3]);
                }
            }

            // ---- scale + mask + row max ----
            float bm[2] = { -INFINITY, -INFINITY };
            #pragma unroll
            for (int h = 0; h < 2; h++) {
                const uint4 m4 = mw[h];
                const unsigned int w = (kb == 0) ? m4.x : (kb == 1) ? m4.y
                                     : (kb == 2) ? m4.z : m4.w;
                #pragma unroll
                for (int nt = 0; nt < 4; nt++) {
                    const unsigned int sh = (unsigned)(8 * nt + 2 * t);
                    const bool b0 = (w >> sh) & 1u;
                    const bool b1 = (w >> (sh + 1)) & 1u;
                    float e0 = sfr[nt][2 * h];
                    float e1 = sfr[nt][2 * h + 1];
                    e0 = b0 ? e0 * 0.125f : -32768.0f;
                    e1 = b1 ? e1 * 0.125f : -32768.0f;
                    sfr[nt][2 * h]     = e0;
                    sfr[nt][2 * h + 1] = e1;
                    bm[h] = fmaxf(bm[h], fmaxf(e0, e1));
                }
            }
            #pragma unroll
            for (int h = 0; h < 2; h++) {
                float x = bm[h];
                x = fmaxf(x, __shfl_xor_sync(0xffffffff, x, 1));
                x = fmaxf(x, __shfl_xor_sync(0xffffffff, x, 2));
                bm[h] = x;
            }

            // ---- online update ----
            float alpha[2];
            float rs[2] = { 0.f, 0.f };
            #pragma unroll
            for (int h = 0; h < 2; h++) {
                const float mnew = fmaxf(mrow[h], bm[h]);
                alpha[h] = __expf(mrow[h] - mnew);   // 0 on first block
                mrow[h] = mnew;
            }

            #pragma unroll
            for (int nt = 0; nt < 4; nt++)
                #pragma unroll
                for (int h = 0; h < 2; h++) {
                    float p0 = __expf(sfr[nt][2 * h]     - mrow[h]);
                    float p1 = __expf(sfr[nt][2 * h + 1] - mrow[h]);
                    sfr[nt][2 * h]     = p0;
                    sfr[nt][2 * h + 1] = p1;
                    rs[h] += p0 + p1;
                }

            #pragma unroll
            for (int h = 0; h < 2; h++) {
                float x = rs[h];
                x += __shfl_xor_sync(0xffffffff, x, 1);
                x += __shfl_xor_sync(0xffffffff, x, 2);
                lrow[h] = lrow[h] * alpha[h] + x;
            }

            #pragma unroll
            for (int nt = 0; nt < 8; nt++) {
                oacc[nt][0] *= alpha[0];
                oacc[nt][1] *= alpha[0];
                oacc[nt][2] *= alpha[1];
                oacc[nt][3] *= alpha[1];
            }

            // P: C-frag pairs ARE the fp16 A-frags
            unsigned int pa[2][4];
            #pragma unroll
            for (int ksp = 0; ksp < 2; ksp++) {
                pa[ksp][0] = h2u(__floats2half2_rn(sfr[2 * ksp][0],     sfr[2 * ksp][1]));
                pa[ksp][1] = h2u(__floats2half2_rn(sfr[2 * ksp][2],     sfr[2 * ksp][3]));
                pa[ksp][2] = h2u(__floats2half2_rn(sfr[2 * ksp + 1][0], sfr[2 * ksp + 1][1]));
                pa[ksp][3] = h2u(__floats2half2_rn(sfr[2 * ksp + 1][2], sfr[2 * ksp + 1][3]));
            }

            // ---- O += P @ V ----
            #pragma unroll
            for (int ksp = 0; ksp < 2; ksp++) {
                #pragma unroll
                for (int dp = 0; dp < 4; dp++) {
                    unsigned int vb4[4];
                    const __half* vp = Vs + (key0 + 16 * ksp + (lane & 15)) * SSTRIDE
                                          + 16 * dp + ((lane & 16) >> 1);
                    ldsm_x4_trans(vb4, vp);
                    mma_f16(oacc[2 * dp],     pa[ksp], vb4[0], vb4[1]);
                    mma_f16(oacc[2 * dp + 1], pa[ksp], vb4[2], vb4[3]);
                }
            }
        }

        // ---- epilogue: normalize and store ----
        {
            const float inv0 = 1.0f / lrow[0];
            const float inv1 = 1.0f / lrow[1];
            const int r0 = 16 * wid + g;
            #pragma unroll
            for (int nt = 0; nt < 8; nt++) {
                const int col = 8 * nt + 2 * t;
                float2 lo = { oacc[nt][0] * inv0, oacc[nt][1] * inv0 };
                float2 hi = { oacc[nt][2] * inv1, oacc[nt][3] * inv1 };
                *(float2*)(out + base + (size_t)(r0)     * DH + col) = lo;
                *(float2*)(out + base + (size_t)(r0 + 8) * DH + col) = hi;
            }
        }
    }

    // drain outstanding async copies before exit
    asm volatile("cp.async.wait_group 0;");
}

extern "C" void kernel_launch(void* const* d_in, const int* in_sizes, int n_in,
                              void* d_out, int out_size)
{
    const float* q    = (const float*)d_in[0];
    const float* k    = (const float*)d_in[1];
    const float* v    = (const float*)d_in[2];
    const int*   mask = (const int*)d_in[3];
    float*       out  = (float*)d_out;

    const int nprob = in_sizes[0] / (LSEQ * DH);     // B*H*N
    const int nmask = in_sizes[3] / (LSEQ * LSEQ);   // B*N
    const int HN    = (nprob / nmask) * LSEQ;        // H*N

    const int nwords = in_sizes[3] / 32;
    const int nwarps = (nwords + 3) / 4;
    pack_mask_kernel<<<(nwarps * 32 + 255) / 256, 256>>>(mask, nwords);

    int nsm = 148;
    cudaDeviceGetAttribute(&nsm, cudaDevAttrMultiProcessorCount, 0);
    int grid = 2 * nsm;
    if (grid > nprob) grid = nprob;

    const int smem_bytes = 2 * TEN * (int)sizeof(__half)     // fp16 K,V  36864
                         + 2 * RINGF * (int)sizeof(float);   // fp32 ring 32768
    cudaFuncSetAttribute(attn_mma_fp16,
                         cudaFuncAttributeMaxDynamicSharedMemorySize,
                         smem_bytes);

    attn_mma_fp16<<<grid, NTHREADS, smem_bytes>>>(q, k, v, out, HN, nprob);
}